// round 11
// baseline (speedup 1.0000x reference)
#include <cuda_runtime.h>
#include <math.h>

#define D      256
#define B      1024
#define NITER  6
#define H4     1024   // 4*D
#define K2     512    // 2*D
#define MAXN   200000

// ---------------- scratch (device globals; no allocation allowed) ----------
__device__ float g_x[B * K2];        // [h | readout] per graph == q_star layout
__device__ float g_c[B * D];         // LSTM cell state
__device__ float g_gates[B * H4];    // GEMM output
__device__ float g_Wt[K2 * H4];      // combined transposed weights [k][j]
__device__ float g_bias[H4];         // b_ih + b_hh
__device__ float g_e[MAXN];          // attention scores
__device__ int   g_seg_start[B + 1];

// ---------------- setup: fold W_ih[:, :D] into W_hh, transpose ------------
__global__ void k_prep_weights(const float* __restrict__ W_ih,
                               const float* __restrict__ W_hh,
                               const float* __restrict__ b_ih,
                               const float* __restrict__ b_hh) {
    int idx = blockIdx.x * blockDim.x + threadIdx.x;
    if (idx < K2 * H4) {
        int k = idx / H4;     // 0..511
        int j = idx % H4;     // 0..1023
        float w = W_ih[j * K2 + k];
        if (k < D) w += W_hh[j * D + k];
        g_Wt[idx] = w;
    }
    if (idx < H4) g_bias[idx] = b_ih[idx] + b_hh[idx];
}

// segment boundaries via binary search (segment_ids sorted)
__global__ void k_seg_bounds(const int* __restrict__ seg, int n) {
    int b = blockIdx.x * blockDim.x + threadIdx.x;
    if (b > B) return;
    if (b == B) { g_seg_start[B] = n; return; }
    int lo = 0, hi = n;
    while (lo < hi) {
        int mid = (lo + hi) >> 1;
        if (seg[mid] < b) lo = mid + 1; else hi = mid;
    }
    g_seg_start[b] = lo;
}

__global__ void k_init_state() {
    int i = blockIdx.x * blockDim.x + threadIdx.x;
    if (i < B * K2) g_x[i] = 0.f;
    if (i < B * D)  g_c[i] = 0.f;
}

// ---------------- SGEMM: gates[B,H4] = g_x[B,K2] * g_Wt[K2,H4] ------------
// BM=BN=64, BK=16, 256 threads, 4x4 per thread
__global__ void k_gemm() {
    __shared__ float As[16][68];   // padded
    __shared__ float Bs[16][64];
    const int tid = threadIdx.x;
    const int m0 = blockIdx.y * 64;
    const int n0 = blockIdx.x * 64;
    const int tx = tid & 15, ty = tid >> 4;

    const int a_m = tid >> 2;          // 0..63
    const int a_k = (tid & 3) * 4;     // 0,4,8,12
    const int b_k = tid >> 4;          // 0..15
    const int b_n = (tid & 15) * 4;    // 0..60

    float acc[4][4];
#pragma unroll
    for (int r = 0; r < 4; r++)
#pragma unroll
        for (int c = 0; c < 4; c++) acc[r][c] = 0.f;

    for (int k0 = 0; k0 < K2; k0 += 16) {
        float4 av = *(const float4*)&g_x[(m0 + a_m) * K2 + k0 + a_k];
        As[a_k + 0][a_m] = av.x;
        As[a_k + 1][a_m] = av.y;
        As[a_k + 2][a_m] = av.z;
        As[a_k + 3][a_m] = av.w;
        *(float4*)&Bs[b_k][b_n] =
            *(const float4*)&g_Wt[(k0 + b_k) * H4 + n0 + b_n];
        __syncthreads();
#pragma unroll
        for (int k = 0; k < 16; k++) {
            float4 a = *(const float4*)&As[k][ty * 4];
            float4 bv = *(const float4*)&Bs[k][tx * 4];
            acc[0][0] += a.x * bv.x; acc[0][1] += a.x * bv.y;
            acc[0][2] += a.x * bv.z; acc[0][3] += a.x * bv.w;
            acc[1][0] += a.y * bv.x; acc[1][1] += a.y * bv.y;
            acc[1][2] += a.y * bv.z; acc[1][3] += a.y * bv.w;
            acc[2][0] += a.z * bv.x; acc[2][1] += a.z * bv.y;
            acc[2][2] += a.z * bv.z; acc[2][3] += a.z * bv.w;
            acc[3][0] += a.w * bv.x; acc[3][1] += a.w * bv.y;
            acc[3][2] += a.w * bv.z; acc[3][3] += a.w * bv.w;
        }
        __syncthreads();
    }
#pragma unroll
    for (int r = 0; r < 4; r++) {
        float4 o = make_float4(acc[r][0], acc[r][1], acc[r][2], acc[r][3]);
        *(float4*)&g_gates[(size_t)(m0 + ty * 4 + r) * H4 + n0 + tx * 4] = o;
    }
}

// ---------------- LSTM pointwise update -----------------------------------
__device__ __forceinline__ float sigf(float x) { return 1.f / (1.f + expf(-x)); }

__global__ void k_lstm(int first) {
    int b = blockIdx.x, t = threadIdx.x;   // 256 threads
    float gi, gf, gg, go;
    if (first) {
        gi = g_bias[t];         gf = g_bias[D + t];
        gg = g_bias[2 * D + t]; go = g_bias[3 * D + t];
    } else {
        const float* row = g_gates + (size_t)b * H4;
        gi = row[t] + g_bias[t];
        gf = row[D + t] + g_bias[D + t];
        gg = row[2 * D + t] + g_bias[2 * D + t];
        go = row[3 * D + t] + g_bias[3 * D + t];
    }
    float c = sigf(gf) * g_c[b * D + t] + sigf(gi) * tanhf(gg);
    float h = sigf(go) * tanhf(c);
    g_c[b * D + t] = c;
    g_x[(size_t)b * K2 + t] = h;   // q == h, first half of q_star
}

// ---------------- segment attention + readout (one CTA per graph) ---------
__global__ void k_attn(const float* __restrict__ feat) {
    __shared__ float sq[D];
    __shared__ float red[8];
    __shared__ float part[8][D];
    const int b = blockIdx.x;
    const int tid = threadIdx.x, lane = tid & 31, warp = tid >> 5;
    const int s = g_seg_start[b], e = g_seg_start[b + 1];

    sq[tid] = g_x[(size_t)b * K2 + tid];
    __syncthreads();

    float4 q0 = *(const float4*)&sq[lane * 4];
    float4 q1 = *(const float4*)&sq[128 + lane * 4];

    // phase 1: e_i = <feat_i, q_b>, track max
    float lmax = -INFINITY;
    for (int i = s + warp; i < e; i += 8) {
        const float4* f = (const float4*)(feat + (size_t)i * D);
        float4 fa = f[lane];
        float4 fb = f[32 + lane];
        float p = fa.x * q0.x + fa.y * q0.y + fa.z * q0.z + fa.w * q0.w
                + fb.x * q1.x + fb.y * q1.y + fb.z * q1.z + fb.w * q1.w;
#pragma unroll
        for (int o = 16; o; o >>= 1) p += __shfl_xor_sync(0xffffffffu, p, o);
        if (lane == 0) g_e[i] = p;
        lmax = fmaxf(lmax, p);
    }
    if (lane == 0) red[warp] = lmax;
    __syncthreads();
    float m = -INFINITY;
#pragma unroll
    for (int w = 0; w < 8; w++) m = fmaxf(m, red[w]);
    __syncthreads();

    // phase 2: denom
    float lsum = 0.f;
    for (int i = s + tid; i < e; i += 256) lsum += expf(g_e[i] - m);
#pragma unroll
    for (int o = 16; o; o >>= 1) lsum += __shfl_xor_sync(0xffffffffu, lsum, o);
    if (lane == 0) red[warp] = lsum;
    __syncthreads();
    float denom = 0.f;
#pragma unroll
    for (int w = 0; w < 8; w++) denom += red[w];
    float inv = (denom > 0.f) ? 1.f / denom : 0.f;

    // phase 3: readout = sum alpha_i * feat_i  (feat re-read, L2-hot)
    float4 r0 = make_float4(0.f, 0.f, 0.f, 0.f);
    float4 r1 = make_float4(0.f, 0.f, 0.f, 0.f);
    for (int i = s + warp; i < e; i += 8) {
        float a = expf(g_e[i] - m) * inv;
        const float4* f = (const float4*)(feat + (size_t)i * D);
        float4 fa = f[lane];
        float4 fb = f[32 + lane];
        r0.x += a * fa.x; r0.y += a * fa.y; r0.z += a * fa.z; r0.w += a * fa.w;
        r1.x += a * fb.x; r1.y += a * fb.y; r1.z += a * fb.z; r1.w += a * fb.w;
    }
    *(float4*)&part[warp][lane * 4]       = r0;
    *(float4*)&part[warp][128 + lane * 4] = r1;
    __syncthreads();
    float rsum = 0.f;
#pragma unroll
    for (int w = 0; w < 8; w++) rsum += part[w][tid];
    g_x[(size_t)b * K2 + D + tid] = rsum;   // second half of q_star
}

__global__ void k_copy_out(float* __restrict__ out) {
    int i = blockIdx.x * blockDim.x + threadIdx.x;
    if (i < B * K2) out[i] = g_x[i];
}

// ---------------- launch ---------------------------------------------------
extern "C" void kernel_launch(void* const* d_in, const int* in_sizes, int n_in,
                              void* d_out, int out_size) {
    const float* feat  = (const float*)d_in[0];
    const float* W_ih  = (const float*)d_in[1];
    const float* W_hh  = (const float*)d_in[2];
    const float* b_ih  = (const float*)d_in[3];
    const float* b_hh  = (const float*)d_in[4];
    const int*   seg   = (const int*)d_in[5];
    const int n = in_sizes[5];   // node count

    k_prep_weights<<<(K2 * H4 + 255) / 256, 256>>>(W_ih, W_hh, b_ih, b_hh);
    k_seg_bounds<<<(B + 256) / 256, 256>>>(seg, n);
    k_init_state<<<(B * K2 + 255) / 256, 256>>>();

    for (int it = 0; it < NITER; it++) {
        if (it > 0) k_gemm<<<dim3(16, 16), 256>>>();
        k_lstm<<<B, 256>>>(it == 0);
        k_attn<<<B, 256>>>(feat);
    }
    k_copy_out<<<(B * K2 + 255) / 256, 256>>>((float*)d_out);
}

// round 17
// speedup vs baseline: 1.1848x; 1.1848x over previous
#include <cuda_runtime.h>
#include <math.h>

#define D      256
#define B      1024
#define NITER  6
#define H4     1024   // 4*D
#define K2     512    // 2*D

// ---------------- scratch (device globals; no allocation allowed) ----------
__device__ float g_x[B * K2];        // [h | readout] per graph == q_star layout
__device__ float g_c[B * D];         // LSTM cell state
__device__ float g_gates[B * H4];    // GEMM output
__device__ float g_Wt[K2 * H4];      // combined transposed weights [k][j]
__device__ float g_bias[H4];         // b_ih + b_hh
__device__ int   g_seg_start[B + 1];

// ---------------- setup: fold W_ih[:, :D] into W_hh, transpose ------------
__global__ void k_prep_weights(const float* __restrict__ W_ih,
                               const float* __restrict__ W_hh,
                               const float* __restrict__ b_ih,
                               const float* __restrict__ b_hh) {
    int idx = blockIdx.x * blockDim.x + threadIdx.x;
    if (idx < K2 * H4) {
        int k = idx / H4;     // 0..511
        int j = idx % H4;     // 0..1023
        float w = W_ih[j * K2 + k];
        if (k < D) w += W_hh[j * D + k];
        g_Wt[idx] = w;
    }
    if (idx < H4) g_bias[idx] = b_ih[idx] + b_hh[idx];
}

// segment boundaries via binary search (segment_ids sorted)
__global__ void k_seg_bounds(const int* __restrict__ seg, int n) {
    int b = blockIdx.x * blockDim.x + threadIdx.x;
    if (b > B) return;
    if (b == B) { g_seg_start[B] = n; return; }
    int lo = 0, hi = n;
    while (lo < hi) {
        int mid = (lo + hi) >> 1;
        if (seg[mid] < b) lo = mid + 1; else hi = mid;
    }
    g_seg_start[b] = lo;
}

__global__ void k_init_state() {
    int i = blockIdx.x * blockDim.x + threadIdx.x;
    if (i < B * K2) g_x[i] = 0.f;
    if (i < B * D)  g_c[i] = 0.f;
}

// ---------------- SGEMM: gates[B,H4] = g_x[B,K2] * g_Wt[K2,H4] ------------
// BM=128, BN=64, BK=16, 256 threads, 8x4 per thread
__global__ void k_gemm() {
    __shared__ float As[16][132];   // [k][m], padded
    __shared__ float Bs[16][64];    // [k][n]
    const int tid = threadIdx.x;
    const int m0 = blockIdx.y * 128;
    const int n0 = blockIdx.x * 64;
    const int tx = tid & 15;        // 0..15  -> 4 cols each
    const int ty = tid >> 4;        // 0..15  -> 8 rows each

    const int a_m = tid >> 1;          // 0..127
    const int a_k = (tid & 1) * 8;     // 0 or 8
    const int b_k = tid >> 4;          // 0..15
    const int b_n = (tid & 15) * 4;    // 0..60

    float acc[8][4];
#pragma unroll
    for (int r = 0; r < 8; r++)
#pragma unroll
        for (int c = 0; c < 4; c++) acc[r][c] = 0.f;

    for (int k0 = 0; k0 < K2; k0 += 16) {
        float4 av0 = *(const float4*)&g_x[(size_t)(m0 + a_m) * K2 + k0 + a_k];
        float4 av1 = *(const float4*)&g_x[(size_t)(m0 + a_m) * K2 + k0 + a_k + 4];
        As[a_k + 0][a_m] = av0.x;
        As[a_k + 1][a_m] = av0.y;
        As[a_k + 2][a_m] = av0.z;
        As[a_k + 3][a_m] = av0.w;
        As[a_k + 4][a_m] = av1.x;
        As[a_k + 5][a_m] = av1.y;
        As[a_k + 6][a_m] = av1.z;
        As[a_k + 7][a_m] = av1.w;
        *(float4*)&Bs[b_k][b_n] =
            *(const float4*)&g_Wt[(size_t)(k0 + b_k) * H4 + n0 + b_n];
        __syncthreads();
#pragma unroll
        for (int k = 0; k < 16; k++) {
            float4 a0 = *(const float4*)&As[k][ty * 8];
            float4 a1 = *(const float4*)&As[k][ty * 8 + 4];
            float4 bv = *(const float4*)&Bs[k][tx * 4];
            acc[0][0] += a0.x * bv.x; acc[0][1] += a0.x * bv.y;
            acc[0][2] += a0.x * bv.z; acc[0][3] += a0.x * bv.w;
            acc[1][0] += a0.y * bv.x; acc[1][1] += a0.y * bv.y;
            acc[1][2] += a0.y * bv.z; acc[1][3] += a0.y * bv.w;
            acc[2][0] += a0.z * bv.x; acc[2][1] += a0.z * bv.y;
            acc[2][2] += a0.z * bv.z; acc[2][3] += a0.z * bv.w;
            acc[3][0] += a0.w * bv.x; acc[3][1] += a0.w * bv.y;
            acc[3][2] += a0.w * bv.z; acc[3][3] += a0.w * bv.w;
            acc[4][0] += a1.x * bv.x; acc[4][1] += a1.x * bv.y;
            acc[4][2] += a1.x * bv.z; acc[4][3] += a1.x * bv.w;
            acc[5][0] += a1.y * bv.x; acc[5][1] += a1.y * bv.y;
            acc[5][2] += a1.y * bv.z; acc[5][3] += a1.y * bv.w;
            acc[6][0] += a1.z * bv.x; acc[6][1] += a1.z * bv.y;
            acc[6][2] += a1.z * bv.z; acc[6][3] += a1.z * bv.w;
            acc[7][0] += a1.w * bv.x; acc[7][1] += a1.w * bv.y;
            acc[7][2] += a1.w * bv.z; acc[7][3] += a1.w * bv.w;
        }
        __syncthreads();
    }
#pragma unroll
    for (int r = 0; r < 8; r++) {
        float4 o = make_float4(acc[r][0], acc[r][1], acc[r][2], acc[r][3]);
        *(float4*)&g_gates[(size_t)(m0 + ty * 8 + r) * H4 + n0 + tx * 4] = o;
    }
}

// ---------------- LSTM pointwise update -----------------------------------
__device__ __forceinline__ float sigf(float x) { return 1.f / (1.f + expf(-x)); }

__global__ void k_lstm(int first) {
    int b = blockIdx.x, t = threadIdx.x;   // 256 threads
    float gi, gf, gg, go;
    if (first) {
        gi = g_bias[t];         gf = g_bias[D + t];
        gg = g_bias[2 * D + t]; go = g_bias[3 * D + t];
    } else {
        const float* row = g_gates + (size_t)b * H4;
        gi = row[t] + g_bias[t];
        gf = row[D + t] + g_bias[D + t];
        gg = row[2 * D + t] + g_bias[2 * D + t];
        go = row[3 * D + t] + g_bias[3 * D + t];
    }
    float c = sigf(gf) * g_c[b * D + t] + sigf(gi) * tanhf(gg);
    float h = sigf(go) * tanhf(c);
    g_c[b * D + t] = c;
    g_x[(size_t)b * K2 + t] = h;   // q == h, first half of q_star
}

// ------- segment attention + readout, ONE-PASS online softmax -------------
// One CTA per graph, 8 warps. Each warp keeps a running (max, sum, readout)
// state over its strided node slice, rescaling on new maxima. feat is read
// exactly once per iteration.
__global__ void k_attn(const float* __restrict__ feat) {
    __shared__ float sq[D];
    __shared__ float wmax[8], wsum[8];
    __shared__ float part[8][D];
    const int b = blockIdx.x;
    const int tid = threadIdx.x, lane = tid & 31, warp = tid >> 5;
    const int s = g_seg_start[b], e = g_seg_start[b + 1];

    sq[tid] = g_x[(size_t)b * K2 + tid];
    __syncthreads();

    float4 q0 = *(const float4*)&sq[lane * 4];
    float4 q1 = *(const float4*)&sq[128 + lane * 4];

    float lmax = -INFINITY, lsum = 0.f;
    float4 r0 = make_float4(0.f, 0.f, 0.f, 0.f);
    float4 r1 = make_float4(0.f, 0.f, 0.f, 0.f);

    for (int i = s + warp; i < e; i += 8) {
        const float4* f = (const float4*)(feat + (size_t)i * D);
        float4 fa = f[lane];
        float4 fb = f[32 + lane];
        float p = fa.x * q0.x + fa.y * q0.y + fa.z * q0.z + fa.w * q0.w
                + fb.x * q1.x + fb.y * q1.y + fb.z * q1.z + fb.w * q1.w;
#pragma unroll
        for (int o = 16; o; o >>= 1) p += __shfl_xor_sync(0xffffffffu, p, o);
        // online softmax update (all lanes hold identical p/lmax/lsum)
        float nm = fmaxf(lmax, p);
        float scale = expf(lmax - nm);   // exp(-inf)=0 on first node
        float w = expf(p - nm);
        lsum = lsum * scale + w;
        r0.x = r0.x * scale + w * fa.x;  r0.y = r0.y * scale + w * fa.y;
        r0.z = r0.z * scale + w * fa.z;  r0.w = r0.w * scale + w * fa.w;
        r1.x = r1.x * scale + w * fb.x;  r1.y = r1.y * scale + w * fb.y;
        r1.z = r1.z * scale + w * fb.z;  r1.w = r1.w * scale + w * fb.w;
        lmax = nm;
    }

    if (lane == 0) { wmax[warp] = lmax; wsum[warp] = lsum; }
    __syncthreads();

    // merge warp states: global max, rescale each warp's partial
    float M = -INFINITY;
#pragma unroll
    for (int w = 0; w < 8; w++) M = fmaxf(M, wmax[w]);
    float denom = 0.f;
#pragma unroll
    for (int w = 0; w < 8; w++) {
        float sc = (wmax[w] == -INFINITY) ? 0.f : expf(wmax[w] - M);
        denom += wsum[w] * sc;
    }
    float mysc = (lmax == -INFINITY) ? 0.f : expf(lmax - M);
    r0.x *= mysc; r0.y *= mysc; r0.z *= mysc; r0.w *= mysc;
    r1.x *= mysc; r1.y *= mysc; r1.z *= mysc; r1.w *= mysc;
    *(float4*)&part[warp][lane * 4]       = r0;
    *(float4*)&part[warp][128 + lane * 4] = r1;
    __syncthreads();

    float inv = (denom > 0.f) ? 1.f / denom : 0.f;
    float rsum = 0.f;
#pragma unroll
    for (int w = 0; w < 8; w++) rsum += part[w][tid];
    g_x[(size_t)b * K2 + D + tid] = rsum * inv;   // second half of q_star
}

__global__ void k_copy_out(float* __restrict__ out) {
    int i = blockIdx.x * blockDim.x + threadIdx.x;
    if (i < B * K2) out[i] = g_x[i];
}

// ---------------- launch ---------------------------------------------------
extern "C" void kernel_launch(void* const* d_in, const int* in_sizes, int n_in,
                              void* d_out, int out_size) {
    const float* feat  = (const float*)d_in[0];
    const float* W_ih  = (const float*)d_in[1];
    const float* W_hh  = (const float*)d_in[2];
    const float* b_ih  = (const float*)d_in[3];
    const float* b_hh  = (const float*)d_in[4];
    const int*   seg   = (const int*)d_in[5];
    const int n = in_sizes[5];   // node count

    k_prep_weights<<<(K2 * H4 + 255) / 256, 256>>>(W_ih, W_hh, b_ih, b_hh);
    k_seg_bounds<<<(B + 256) / 256, 256>>>(seg, n);
    k_init_state<<<(B * K2 + 255) / 256, 256>>>();

    for (int it = 0; it < NITER; it++) {
        if (it > 0) k_gemm<<<dim3(16, 8), 256>>>();
        k_lstm<<<B, 256>>>(it == 0);
        k_attn<<<B, 256>>>(feat);
    }
    k_copy_out<<<(B * K2 + 255) / 256, 256>>>((float*)d_out);
}